// round 4
// baseline (speedup 1.0000x reference)
#include <cuda_runtime.h>
#include <cuda_bf16.h>

// GraphAddPooling: out[g] = sum_{i: batch[i]==g} x[i]
// x: [200000, 256] fp32, batch: sorted (int32 or int64, detected), out: [512,256] fp32.
//
// R1's proven streaming engine (contiguous 169-row chunks, 1184 blocks = exactly
// 8 CTAs/SM, register-accumulate + segment-boundary atomics, 73.5% DRAM) with the
// output zeroing FOLDED INTO THE SAME LAUNCH:
//   - blocks 0..NZB-1 zero their slice of out, fence, bump g_ready
//   - every thread spins on g_ready==NZB once, before its FIRST flush only
//     (zeroing finishes ~0.5us in; first flushes ~1us in -> spin ~never waits)
//   - last block to finish resets the counters for the next graph replay

#define NCOLS 256
#define VCOLS (NCOLS / 4)
#define RPB 169             // rows per block
#define GRID_MAIN 1184      // ceil(200000/169); exactly 8 CTAs/SM on 148 SMs
#define TPB 256

__device__ int g_ready = 0;
__device__ int g_finish = 0;

__device__ __forceinline__ void wait_ready(int nzb, bool& ok) {
    if (!ok) {
        while (*(volatile int*)&g_ready < nzb) { }
        __threadfence();   // order the zero-stores before our atomics
        ok = true;
    }
}

__global__ __launch_bounds__(TPB, 8) void gap_fused_kernel(
    const float4* __restrict__ x,
    const int* __restrict__ b32,   // batch viewed as int32 words
    float* __restrict__ out,
    int nrows, int n4, int nzb)
{
    const int lane = threadIdx.x;            // 0..63 : float4 column group
    const int ys   = threadIdx.y;            // 0..3  : row stream
    const int ft   = ys * 64 + lane;         // flat tid

    // ---- fused zeroing: blocks [0, nzb) clear the poisoned output ----
    if (blockIdx.x < (unsigned)nzb) {
        int i = blockIdx.x * TPB + ft;
        if (i < n4) ((float4*)out)[i] = make_float4(0.f, 0.f, 0.f, 0.f);
        __threadfence();
        __syncthreads();
        if (ft == 0) atomicAdd(&g_ready, 1);
    }

    // int64 vs int32 batch: sorted ids < 512, so if stored little-endian
    // int64, the int32 word at index nrows-1 is a high word (== 0).
    const int shift = (b32[nrows - 1] == 0) ? 1 : 0;

    int start = blockIdx.x * RPB;
    int end   = start + RPB;
    if (end > nrows) end = nrows;

    bool ready_ok = false;
    float4 acc = make_float4(0.f, 0.f, 0.f, 0.f);
    int cur = -1;

    int r = start + ys;
    int g = 0;
    float4 v = make_float4(0.f, 0.f, 0.f, 0.f);
    if (r < end) {
        g = b32[r << shift];
        v = x[(size_t)r * VCOLS + lane];
    }

    while (r < end) {
        // Prefetch next iteration (MLP=2).
        int rn = r + 4;
        int gn = 0;
        float4 vn = make_float4(0.f, 0.f, 0.f, 0.f);
        if (rn < end) {
            gn = b32[rn << shift];
            vn = x[(size_t)rn * VCOLS + lane];
        }

        if (g != cur) {
            if (cur >= 0) {
                wait_ready(nzb, ready_ok);
                float* o = out + (size_t)cur * NCOLS + lane * 4;
                atomicAdd(o + 0, acc.x);
                atomicAdd(o + 1, acc.y);
                atomicAdd(o + 2, acc.z);
                atomicAdd(o + 3, acc.w);
            }
            cur = g;
            acc = v;
        } else {
            acc.x += v.x; acc.y += v.y; acc.z += v.z; acc.w += v.w;
        }

        r = rn; g = gn; v = vn;
    }

    if (cur >= 0) {
        wait_ready(nzb, ready_ok);
        float* o = out + (size_t)cur * NCOLS + lane * 4;
        atomicAdd(o + 0, acc.x);
        atomicAdd(o + 1, acc.y);
        atomicAdd(o + 2, acc.z);
        atomicAdd(o + 3, acc.w);
    }

    // ---- replay-safe counter reset: last finishing block cleans up ----
    __syncthreads();
    if (ft == 0) {
        int d = atomicAdd(&g_finish, 1);
        if (d == (int)gridDim.x - 1) {
            g_ready  = 0;
            g_finish = 0;
            __threadfence();
        }
    }
}

extern "C" void kernel_launch(void* const* d_in, const int* in_sizes, int n_in,
                              void* d_out, int out_size) {
    const float4* x  = (const float4*)d_in[0];
    const int* batch = (const int*)d_in[1];
    float* out       = (float*)d_out;

    const int nrows = in_sizes[1];          // 200000
    const int n4    = out_size / 4;         // 32768 float4
    const int nzb   = (n4 + TPB - 1) / TPB; // 128 zeroing blocks

    dim3 block(64, 4);
    gap_fused_kernel<<<GRID_MAIN, block>>>(x, batch, out, nrows, n4, nzb);
}